// round 9
// baseline (speedup 1.0000x reference)
#include <cuda_runtime.h>
#include <cstdint>
#include <math.h>

// ============================================================================
// Problem constants
// ============================================================================
#define N_ROWS   30000
#define D_IN     784
#define N_CLS    10
#define NC       100
#define MAXK     12
#define INITB    4000
#define BINC     2166
#define NBUCK    4096
#define WSZ      (D_IN * NC)       // 78400 W elements per iteration

// ============================================================================
// Device globals
// ============================================================================
__device__ uint2 dk_wA[MAXK], dk_bA[MAXK];   // per-iteration subkeys
__device__ uint2 dk_skA[MAXK][2];            // per-iteration sort subkeys

__device__ unsigned long long d_pack[N_ROWS];
__device__ unsigned long long d_pack2[N_ROWS];
__device__ unsigned int d_hist[NBUCK];       // zero-init; self-zeroed by k_bsort
__device__ unsigned int d_offs[NBUCK];
__device__ unsigned int d_woffs[NBUCK];
__device__ int d_perm[N_ROWS];

__device__ float d_Wr[MAXK * WSZ];
__device__ float d_br[MAXK * NC];
__device__ float d_H[N_ROWS * MAXK];
__device__ float d_part[870 * 1104];
__device__ int   d_best;
__device__ double d_gpart[125 * 32];
__device__ double d_G[144];                  // persistent, incrementally filled
__device__ double d_C[120];
__device__ float d_beta[MAXK * N_CLS];

// ============================================================================
// JAX Threefry-2x32 (partitionable variant, bit-exact)
// ============================================================================
__device__ __forceinline__ uint32_t rotl32(uint32_t x, int r) {
    return (x << r) | (x >> (32 - r));
}

__device__ __forceinline__ void tf2x32(uint32_t k0, uint32_t k1,
                                       uint32_t x0, uint32_t x1,
                                       uint32_t& o0, uint32_t& o1) {
    uint32_t ks2 = k0 ^ k1 ^ 0x1BD11BDAu;
    x0 += k0; x1 += k1;
#define TFR(r) { x0 += x1; x1 = rotl32(x1, r); x1 ^= x0; }
    TFR(13) TFR(15) TFR(26) TFR(6)   x0 += k1;  x1 += ks2 + 1u;
    TFR(17) TFR(29) TFR(16) TFR(24)  x0 += ks2; x1 += k0  + 2u;
    TFR(13) TFR(15) TFR(26) TFR(6)   x0 += k0;  x1 += k1  + 3u;
    TFR(17) TFR(29) TFR(16) TFR(24)  x0 += k1;  x1 += ks2 + 4u;
    TFR(13) TFR(15) TFR(26) TFR(6)   x0 += ks2; x1 += k0  + 5u;
#undef TFR
    o0 = x0; o1 = x1;
}

__device__ __forceinline__ uint32_t rbits(uint2 key, uint32_t i) {
    uint32_t o0, o1;
    tf2x32(key.x, key.y, 0u, i, o0, o1);
    return o0 ^ o1;
}

__device__ __forceinline__ uint2 subkey(uint2 key, uint32_t j) {
    uint2 r;
    tf2x32(key.x, key.y, 0u, j, r.x, r.y);
    return r;
}

__device__ __forceinline__ float uni01(uint32_t bits) {
    return __uint_as_float((bits >> 9) | 0x3f800000u) - 1.0f;
}

// ============================================================================
// One-time setup: full key chain for all 12 iterations
// ============================================================================
__global__ void k_init() {
    if (threadIdx.x != 0) return;
    uint2 key = make_uint2(0u, 42u);           // jax.random.key(42)
    for (int k = 0; k < MAXK; k++) {
        uint2 nk    = subkey(key, 0);
        uint2 kperm = subkey(key, 1);
        dk_wA[k]    = subkey(key, 2);
        dk_bA[k]    = subkey(key, 3);
        key = nk;
        uint2 kp1    = subkey(kperm, 0);
        dk_skA[k][0] = subkey(kperm, 1);
        dk_skA[k][1] = subkey(kp1,   1);
    }
}

// All 12 iterations' W_random / b_random in one launch.
__global__ void k_genc_all() {
    int e = blockIdx.x * blockDim.x + threadIdx.x;
    if (e >= MAXK * (WSZ + NC)) return;
    int k = e / (WSZ + NC);
    int j = e % (WSZ + NC);
    if (j < WSZ) {
        float u = uni01(rbits(dk_wA[k], (uint32_t)j));
        float lam = ((j % NC) < 50) ? 1.0f : 10.0f;
        d_Wr[k * WSZ + j] = lam * (2.0f * u - 1.0f);
    } else {
        int jj = j - WSZ;
        float u = uni01(rbits(dk_bA[k], (uint32_t)jj));
        float lam = (jj < 50) ? 1.0f : 10.0f;
        d_br[k * NC + jj] = lam * (2.0f * u - 1.0f);
    }
}

// ============================================================================
// Permutation pipeline (stable double-sort, bucketed)
// ============================================================================
__global__ void k_genhist(int k, int round) {
    int i = blockIdx.x * blockDim.x + threadIdx.x;
    if (i >= N_ROWS) return;
    uint32_t key = rbits(dk_skA[k][round], (uint32_t)i);
    uint32_t val = (round == 0) ? (uint32_t)i : (uint32_t)d_perm[i];
    unsigned long long p = ((unsigned long long)key << 30) |
                           ((unsigned long long)(uint32_t)i << 15) |
                           (unsigned long long)val;
    d_pack[i] = p;
    atomicAdd(&d_hist[key >> 20], 1u);
}

// Exclusive scan of 4096 bins (1 block, 1024 threads, shfl-based).
__global__ void k_scan() {
    __shared__ unsigned int wsum[32];
    int t = threadIdx.x;
    unsigned int h0[4], s = 0;
#pragma unroll
    for (int j = 0; j < 4; j++) { h0[j] = d_hist[t * 4 + j]; s += h0[j]; }
    int lane = t & 31, wid = t >> 5;
    unsigned int v = s;
#pragma unroll
    for (int o = 1; o < 32; o <<= 1) {
        unsigned int u = __shfl_up_sync(0xffffffffu, v, o);
        if (lane >= o) v += u;
    }
    if (lane == 31) wsum[wid] = v;
    __syncthreads();
    if (wid == 0) {
        unsigned int w = wsum[lane];
#pragma unroll
        for (int o = 1; o < 32; o <<= 1) {
            unsigned int u = __shfl_up_sync(0xffffffffu, w, o);
            if (lane >= o) w += u;
        }
        wsum[lane] = w;
    }
    __syncthreads();
    unsigned int base = v - s + (wid > 0 ? wsum[wid - 1] : 0u);
#pragma unroll
    for (int j = 0; j < 4; j++) {
        d_offs[t * 4 + j]  = base;
        d_woffs[t * 4 + j] = base;
        base += h0[j];
    }
}

__global__ void k_scatter() {
    int i = blockIdx.x * blockDim.x + threadIdx.x;
    if (i >= N_ROWS) return;
    unsigned long long p = d_pack[i];
    unsigned int b = (unsigned int)(p >> 50);
    unsigned int pos = atomicAdd(&d_woffs[b], 1u);
    d_pack2[pos] = p;
}

// Per-bucket insertion sort; also re-zeroes d_hist for the next round.
__global__ void k_bsort() {
    int b = blockIdx.x * blockDim.x + threadIdx.x;
    if (b >= NBUCK) return;
    unsigned int start = d_offs[b];
    unsigned int cnt = d_hist[b];
    if (cnt > 64u) cnt = 64u;
    unsigned long long a[64];
    for (unsigned int i = 0; i < cnt; i++) a[i] = d_pack2[start + i];
    for (unsigned int i = 1; i < cnt; i++) {
        unsigned long long key = a[i];
        int j = (int)i - 1;
        while (j >= 0 && a[j] > key) { a[j + 1] = a[j]; j--; }
        a[j + 1] = key;
    }
    for (unsigned int i = 0; i < cnt; i++)
        d_perm[start + i] = (int)(a[i] & 0x7FFFull);
    d_hist[b] = 0u;
}

// ============================================================================
// Candidate evaluation: 32 rows x 100 candidates per block, 200 threads,
// 4x4 register tile. ek computed in-kernel from H and beta (y = H @ beta).
// ============================================================================
#define BM 32
#define KT 56
#define NTILE (D_IN / KT)   // 14

__global__ void __launch_bounds__(200, 5)
k_cand(const float* __restrict__ X, const float* __restrict__ Y,
       int batch, int n /* = k: columns in H / rows in beta */, int kit) {
    __shared__ float As[KT][36];       // transposed A tile (pad 36)
    __shared__ float Bs[KT][NC];
    __shared__ float ekS[BM][N_CLS];
    __shared__ float betaS[MAXK * N_CLS];
    __shared__ int idxS[BM];

    int tid = threadIdx.x;
    int tx = tid >> 3;                 // 0..24 candidate group (4 cands)
    int ty = tid & 7;                  // 0..7 row group (4 rows)
    int row0 = blockIdx.x * BM;
    const float* Wit = d_Wr + kit * WSZ;

    if (tid < BM) {
        int g = row0 + tid;
        idxS[tid] = (g < batch) ? d_perm[g] : -1;
    }
    if (tid >= 64 && tid < 64 + n * N_CLS) betaS[tid - 64] = d_beta[tid - 64];
    __syncthreads();
    // ek = Y[idx] - H[idx, :n] @ beta   (ascending-q order, matches reference)
    for (int t = tid; t < BM * N_CLS; t += 200) {
        int r = t / N_CLS, j = t % N_CLS;
        int idx = idxS[r];
        float e = 0.0f;
        if (idx >= 0) {
            float yv = 0.0f;
            const float* hr = d_H + (size_t)idx * MAXK;
            for (int q = 0; q < n; q++) yv += hr[q] * betaS[q * N_CLS + j];
            e = Y[idx * N_CLS + j] - yv;
        }
        ekS[r][j] = e;
    }

    float acc[16];
#pragma unroll
    for (int i = 0; i < 16; i++) acc[i] = 0.0f;

    for (int t14 = 0; t14 < NTILE; t14++) {
        int k0 = t14 * KT;
        __syncthreads();
        // A tile: 32 rows x 56 k, transposed into As[k][r]
        for (int e = tid; e < BM * (KT / 4); e += 200) {
            int r = e / (KT / 4);
            int v = e % (KT / 4);
            int idx = idxS[r];
            float4 x = make_float4(0.f, 0.f, 0.f, 0.f);
            if (idx >= 0)
                x = *reinterpret_cast<const float4*>(X + (size_t)idx * D_IN + k0 + v * 4);
            As[v * 4 + 0][r] = x.x;
            As[v * 4 + 1][r] = x.y;
            As[v * 4 + 2][r] = x.z;
            As[v * 4 + 3][r] = x.w;
        }
        // B tile: flat float4 copy
        {
            const float4* src = reinterpret_cast<const float4*>(Wit + k0 * NC);
            float4* dst = reinterpret_cast<float4*>(&Bs[0][0]);
            for (int e = tid; e < KT * NC / 4; e += 200) dst[e] = src[e];
        }
        __syncthreads();
#pragma unroll 8
        for (int q = 0; q < KT; q++) {
            float4 a = *reinterpret_cast<const float4*>(&As[q][ty * 4]);
            float4 b = *reinterpret_cast<const float4*>(&Bs[q][tx * 4]);
            acc[0]  += a.x * b.x;  acc[1]  += a.x * b.y;
            acc[2]  += a.x * b.z;  acc[3]  += a.x * b.w;
            acc[4]  += a.y * b.x;  acc[5]  += a.y * b.y;
            acc[6]  += a.y * b.z;  acc[7]  += a.y * b.w;
            acc[8]  += a.z * b.x;  acc[9]  += a.z * b.y;
            acc[10] += a.z * b.z;  acc[11] += a.z * b.w;
            acc[12] += a.w * b.x;  acc[13] += a.w * b.y;
            acc[14] += a.w * b.z;  acc[15] += a.w * b.w;
        }
    }

    // Epilogue: h = sigmoid(acc + bias), masked.
    const float* bit = d_br + kit * NC;
    float bj[4];
#pragma unroll
    for (int j = 0; j < 4; j++) bj[j] = bit[tx * 4 + j];
    bool vld[4];
#pragma unroll
    for (int i = 0; i < 4; i++) vld[i] = (idxS[ty * 4 + i] >= 0);

    float h[16];
#pragma unroll
    for (int i = 0; i < 4; i++)
#pragma unroll
        for (int j = 0; j < 4; j++) {
            float z = acc[i * 4 + j] + bj[j];
            h[i * 4 + j] = vld[i] ? (1.0f / (1.0f + expf(-z))) : 0.0f;
        }

    // 8-lane group reductions (groups of ty within a warp); warp 6 is 8 lanes.
    int lane = tid & 31;
    unsigned int msk = 0xFFu << (lane & ~7);
    int pbase = blockIdx.x * 1104 + (tx * 4) * 11;

#pragma unroll
    for (int j = 0; j < 4; j++) {
        float s2 = h[j] * h[j] + h[4 + j] * h[4 + j] +
                   h[8 + j] * h[8 + j] + h[12 + j] * h[12 + j];
#pragma unroll
        for (int o = 1; o < 8; o <<= 1) s2 += __shfl_xor_sync(msk, s2, o);
        if (ty == 0) d_part[pbase + j * 11 + 10] = s2;
    }
#pragma unroll
    for (int jc = 0; jc < N_CLS; jc++) {
        float e0 = ekS[ty * 4 + 0][jc];
        float e1 = ekS[ty * 4 + 1][jc];
        float e2 = ekS[ty * 4 + 2][jc];
        float e3 = ekS[ty * 4 + 3][jc];
#pragma unroll
        for (int j = 0; j < 4; j++) {
            float m = e0 * h[j] + e1 * h[4 + j] + e2 * h[8 + j] + e3 * h[12 + j];
#pragma unroll
            for (int o = 1; o < 8; o <<= 1) m += __shfl_xor_sync(msk, m, o);
            if (ty == 0) d_part[pbase + j * 11 + jc] = m;
        }
    }
}

// Final reduce of partials + v + argmax. 800 threads: 100 cands x 8 strides.
__global__ void k_vred(int nb) {
    __shared__ float v[NC];
    int tid = threadIdx.x;
    int c = tid >> 3, p = tid & 7;
    double m[N_CLS];
    double s2 = 0.0;
    for (int j = 0; j < N_CLS; j++) m[j] = 0.0;
    for (int b = p; b < nb; b += 8) {
        const float* pp = &d_part[b * 1104 + c * 11];
        for (int j = 0; j < N_CLS; j++) m[j] += (double)pp[j];
        s2 += (double)pp[10];
    }
    for (int j = 0; j < N_CLS; j++) {
        m[j] += __shfl_xor_sync(0xffffffffu, m[j], 1);
        m[j] += __shfl_xor_sync(0xffffffffu, m[j], 2);
        m[j] += __shfl_xor_sync(0xffffffffu, m[j], 4);
    }
    s2 += __shfl_xor_sync(0xffffffffu, s2, 1);
    s2 += __shfl_xor_sync(0xffffffffu, s2, 2);
    s2 += __shfl_xor_sync(0xffffffffu, s2, 4);
    if (p == 0) {
        double num = 0.0;
        for (int j = 0; j < N_CLS; j++) num += m[j] * m[j];
        v[c] = (float)(num / (10.0 * s2));
    }
    __syncthreads();
    if (tid == 0) {
        float best = -1.0f;
        int bi = 0;
        for (int i = 0; i < NC; i++)
            if (v[i] > best) { best = v[i]; bi = i; }
        d_best = bi;
    }
}

// h_c = sigmoid(X @ W_best + b_best) over all rows; emits W,b outputs.
__global__ void k_hc(const float* __restrict__ X, float* __restrict__ out, int kit) {
    __shared__ float Wc[D_IN];
    __shared__ float s_b;
    int best = d_best;
    const float* Wit = d_Wr + kit * WSZ;
    for (int t = threadIdx.x; t < D_IN; t += 256) Wc[t] = Wit[t * NC + best];
    if (threadIdx.x == 0) s_b = d_br[kit * NC + best];
    __syncthreads();
    int w = threadIdx.x >> 5, lane = threadIdx.x & 31;
    int row = blockIdx.x * 8 + w;
    if (row < N_ROWS) {
        const float* xr = X + (size_t)row * D_IN;
        float s = 0.0f;
        for (int q = lane; q < D_IN; q += 32) s += xr[q] * Wc[q];
#pragma unroll
        for (int o = 16; o; o >>= 1) s += __shfl_down_sync(0xffffffffu, s, o);
        if (lane == 0) {
            float h = 1.0f / (1.0f + expf(-(s + s_b)));
            d_H[row * MAXK + kit] = h;
        }
    }
    if (blockIdx.x == 0) {
        for (int t = threadIdx.x; t < D_IN; t += 256) out[t * MAXK + kit] = Wc[t];
        if (threadIdx.x == 0) out[D_IN * MAXK + kit] = s_b;
    }
}

// Incremental Gram: only the new row/col k of H^T H and row k of H^T Y.
// 125 blocks x 240 rows; 256 threads = 32 entries x 8 row-strides.
__global__ void k_gram_inc(const float* __restrict__ Y, int kit) {
    int tid = threadIdx.x;
    int entry = tid >> 3, s = tid & 7;
    int nent = (kit + 1) + N_CLS;
    double acc = 0.0;
    int r0 = blockIdx.x * 240;
    if (entry < nent) {
        if (entry <= kit) {
            for (int i = 0; i < 30; i++) {
                int r = r0 + s + 8 * i;
                double hk = (double)d_H[r * MAXK + kit];
                acc += hk * (double)d_H[r * MAXK + entry];
            }
        } else {
            int cls = entry - (kit + 1);
            for (int i = 0; i < 30; i++) {
                int r = r0 + s + 8 * i;
                double hk = (double)d_H[r * MAXK + kit];
                acc += hk * (double)Y[r * N_CLS + cls];
            }
        }
    }
    acc += __shfl_xor_sync(0xffffffffu, acc, 1);
    acc += __shfl_xor_sync(0xffffffffu, acc, 2);
    acc += __shfl_xor_sync(0xffffffffu, acc, 4);
    if (s == 0) d_gpart[blockIdx.x * 32 + entry] = acc;
}

// Fused: reduce gram partials -> update d_G/d_C -> Cholesky -> solve beta.
__global__ void k_solve(float* __restrict__ out, int n) {
    __shared__ double Ls[12][12], Cs[12][10];
    int t = threadIdx.x;   // 64
    int nent = n + N_CLS;
    if (t < 32 && t < nent) {
        double a0 = 0, a1 = 0, a2 = 0, a3 = 0, a4 = 0;
        int b = 0;
        for (; b + 5 <= 125; b += 5) {
            a0 += d_gpart[(b + 0) * 32 + t];
            a1 += d_gpart[(b + 1) * 32 + t];
            a2 += d_gpart[(b + 2) * 32 + t];
            a3 += d_gpart[(b + 3) * 32 + t];
            a4 += d_gpart[(b + 4) * 32 + t];
        }
        double sum = ((a0 + a1) + (a2 + a3)) + a4;
        if (t < n) {
            d_G[(n - 1) * 12 + t] = sum;
            d_G[t * 12 + (n - 1)] = sum;
        } else {
            d_C[(n - 1) * 10 + (t - n)] = sum;
        }
    }
    __syncthreads();
    for (int e = t; e < n * n; e += 64) Ls[e / n][e % n] = d_G[(e / n) * 12 + (e % n)];
    for (int e = t; e < n * 10; e += 64) Cs[e / 10][e % 10] = d_C[e];
    __syncthreads();
    if (t < 32) {
        for (int j = 0; j < n; j++) {
            if (t == 0) {
                double s = Ls[j][j];
                for (int p = 0; p < j; p++) s -= Ls[j][p] * Ls[j][p];
                Ls[j][j] = sqrt(s);
            }
            __syncwarp();
            if (t > j && t < n) {
                double s = Ls[t][j];
                for (int p = 0; p < j; p++) s -= Ls[t][p] * Ls[j][p];
                Ls[t][j] = s / Ls[j][j];
            }
            __syncwarp();
        }
    }
    __syncthreads();
    if (t < N_CLS) {
        double z[12];
        for (int i = 0; i < n; i++) {
            double s = Cs[i][t];
            for (int p = 0; p < i; p++) s -= Ls[i][p] * z[p];
            z[i] = s / Ls[i][i];
        }
        for (int i = n - 1; i >= 0; i--) {
            double s = z[i];
            for (int p = i + 1; p < n; p++) s -= Ls[p][i] * z[p];
            z[i] = s / Ls[i][i];
        }
        for (int i = 0; i < n; i++) {
            d_beta[i * 10 + t] = (float)z[i];
            if (n == MAXK) out[D_IN * MAXK + MAXK + i * 10 + t] = (float)z[i];
        }
    }
}

// ============================================================================
// Launch
// ============================================================================
extern "C" void kernel_launch(void* const* d_in, const int* in_sizes, int n_in,
                              void* d_out, int out_size) {
    const float* X = (const float*)d_in[0];
    const float* Y = (const float*)d_in[1];
    float* out = (float*)d_out;

    k_init<<<1, 32>>>();
    k_genc_all<<<(MAXK * (WSZ + NC) + 255) / 256, 256>>>();

    int batch = INITB;
    for (int k = 0; k < MAXK; k++) {
        for (int r = 0; r < 2; r++) {
            k_genhist<<<(N_ROWS + 255) / 256, 256>>>(k, r);
            k_scan<<<1, 1024>>>();
            k_scatter<<<(N_ROWS + 255) / 256, 256>>>();
            k_bsort<<<NBUCK / 128, 128>>>();
        }
        int nb = (batch + BM - 1) / BM;
        k_cand<<<nb, 200>>>(X, Y, batch, k, k);
        k_vred<<<1, 800>>>(nb);
        k_hc<<<(N_ROWS + 7) / 8, 256>>>(X, out, k);
        k_gram_inc<<<125, 256>>>(Y, k);
        k_solve<<<1, 64>>>(out, k + 1);
        batch += BINC;
    }
}

// round 10
// speedup vs baseline: 1.5857x; 1.5857x over previous
#include <cuda_runtime.h>
#include <cstdint>
#include <math.h>

// ============================================================================
// Problem constants
// ============================================================================
#define N_ROWS   30000
#define D_IN     784
#define N_CLS    10
#define NC       100
#define MAXK     12
#define INITB    4000
#define BINC     2166
#define NBUCK    4096
#define WSZ      (D_IN * NC)       // 78400 W elements per iteration

// ============================================================================
// Device globals
// ============================================================================
__device__ uint2 dk_wA[MAXK], dk_bA[MAXK];
__device__ uint2 dk_skA[MAXK][2];

// Batched sort buffers (all 12 iterations at once)
__device__ unsigned long long d_packA[MAXK * N_ROWS];
__device__ unsigned long long d_pack2A[MAXK * N_ROWS];
__device__ unsigned int d_histA[MAXK * NBUCK];   // static zero-init; self-zeroed
__device__ unsigned int d_offsA[MAXK * NBUCK];
__device__ unsigned int d_woffsA[MAXK * NBUCK];
__device__ int d_permA[MAXK * N_ROWS];

__device__ float d_Wr[MAXK * WSZ];               // row-major  [d][c]
__device__ float d_WrT[MAXK * NC * D_IN];        // col-major  [c][d]
__device__ float d_br[MAXK * NC];
__device__ float d_H[N_ROWS * MAXK];
__device__ float d_part[436 * 1104];
__device__ int   d_best;
__device__ double d_gpart[125 * 32];
__device__ double d_G[144];                      // persistent, incremental
__device__ double d_C[120];
__device__ float d_beta[MAXK * N_CLS];
__device__ int d_ctr1;                           // k_cand last-block counter
__device__ int d_ctr2;                           // k_gram last-block counter

// ============================================================================
// JAX Threefry-2x32 (partitionable variant, bit-exact)
// ============================================================================
__device__ __forceinline__ uint32_t rotl32(uint32_t x, int r) {
    return (x << r) | (x >> (32 - r));
}

__device__ __forceinline__ void tf2x32(uint32_t k0, uint32_t k1,
                                       uint32_t x0, uint32_t x1,
                                       uint32_t& o0, uint32_t& o1) {
    uint32_t ks2 = k0 ^ k1 ^ 0x1BD11BDAu;
    x0 += k0; x1 += k1;
#define TFR(r) { x0 += x1; x1 = rotl32(x1, r); x1 ^= x0; }
    TFR(13) TFR(15) TFR(26) TFR(6)   x0 += k1;  x1 += ks2 + 1u;
    TFR(17) TFR(29) TFR(16) TFR(24)  x0 += ks2; x1 += k0  + 2u;
    TFR(13) TFR(15) TFR(26) TFR(6)   x0 += k0;  x1 += k1  + 3u;
    TFR(17) TFR(29) TFR(16) TFR(24)  x0 += k1;  x1 += ks2 + 4u;
    TFR(13) TFR(15) TFR(26) TFR(6)   x0 += ks2; x1 += k0  + 5u;
#undef TFR
    o0 = x0; o1 = x1;
}

__device__ __forceinline__ uint32_t rbits(uint2 key, uint32_t i) {
    uint32_t o0, o1;
    tf2x32(key.x, key.y, 0u, i, o0, o1);
    return o0 ^ o1;
}

__device__ __forceinline__ uint2 subkey(uint2 key, uint32_t j) {
    uint2 r;
    tf2x32(key.x, key.y, 0u, j, r.x, r.y);
    return r;
}

__device__ __forceinline__ float uni01(uint32_t bits) {
    return __uint_as_float((bits >> 9) | 0x3f800000u) - 1.0f;
}

// ============================================================================
// Setup: key chain + all W/b (row-major AND transposed)
// ============================================================================
__global__ void k_init() {
    if (threadIdx.x != 0) return;
    uint2 key = make_uint2(0u, 42u);           // jax.random.key(42)
    for (int k = 0; k < MAXK; k++) {
        uint2 nk    = subkey(key, 0);
        uint2 kperm = subkey(key, 1);
        dk_wA[k]    = subkey(key, 2);
        dk_bA[k]    = subkey(key, 3);
        key = nk;
        uint2 kp1    = subkey(kperm, 0);
        dk_skA[k][0] = subkey(kperm, 1);
        dk_skA[k][1] = subkey(kp1,   1);
    }
}

__global__ void k_genc_all() {
    int e = blockIdx.x * blockDim.x + threadIdx.x;
    if (e >= MAXK * (WSZ + NC)) return;
    int k = e / (WSZ + NC);
    int j = e % (WSZ + NC);
    if (j < WSZ) {
        float u = uni01(rbits(dk_wA[k], (uint32_t)j));
        int col = j % NC, row = j / NC;
        float lam = (col < 50) ? 1.0f : 10.0f;
        float val = lam * (2.0f * u - 1.0f);
        d_Wr[k * WSZ + j] = val;
        d_WrT[(k * NC + col) * D_IN + row] = val;
    } else {
        int jj = j - WSZ;
        float u = uni01(rbits(dk_bA[k], (uint32_t)jj));
        float lam = (jj < 50) ? 1.0f : 10.0f;
        d_br[k * NC + jj] = lam * (2.0f * u - 1.0f);
    }
}

// ============================================================================
// Batched permutation pipeline: all 12 iterations per launch.
// round 0 permutes iota; round 1 permutes round-0's output. Stable via
// 62-bit composite (key:32 | pos:15 | val:15) + per-bucket insertion sort.
// ============================================================================
__global__ void k_genhist_all(int round) {
    int i = blockIdx.x * blockDim.x + threadIdx.x;
    int it = blockIdx.y;
    if (i >= N_ROWS) return;
    uint32_t key = rbits(dk_skA[it][round], (uint32_t)i);
    uint32_t val = (round == 0) ? (uint32_t)i : (uint32_t)d_permA[it * N_ROWS + i];
    unsigned long long p = ((unsigned long long)key << 30) |
                           ((unsigned long long)(uint32_t)i << 15) |
                           (unsigned long long)val;
    d_packA[it * N_ROWS + i] = p;
    atomicAdd(&d_histA[it * NBUCK + (key >> 20)], 1u);
}

// One block per iteration scans its 4096 bins (shfl-based, 2 syncs).
__global__ void k_scan_all() {
    __shared__ unsigned int wsum[32];
    int it = blockIdx.x;
    int t = threadIdx.x;
    const unsigned int* hist = d_histA + it * NBUCK;
    unsigned int h0[4], s = 0;
#pragma unroll
    for (int j = 0; j < 4; j++) { h0[j] = hist[t * 4 + j]; s += h0[j]; }
    int lane = t & 31, wid = t >> 5;
    unsigned int v = s;
#pragma unroll
    for (int o = 1; o < 32; o <<= 1) {
        unsigned int u = __shfl_up_sync(0xffffffffu, v, o);
        if (lane >= o) v += u;
    }
    if (lane == 31) wsum[wid] = v;
    __syncthreads();
    if (wid == 0) {
        unsigned int w = wsum[lane];
#pragma unroll
        for (int o = 1; o < 32; o <<= 1) {
            unsigned int u = __shfl_up_sync(0xffffffffu, w, o);
            if (lane >= o) w += u;
        }
        wsum[lane] = w;
    }
    __syncthreads();
    unsigned int base = v - s + (wid > 0 ? wsum[wid - 1] : 0u);
#pragma unroll
    for (int j = 0; j < 4; j++) {
        d_offsA[it * NBUCK + t * 4 + j]  = base;
        d_woffsA[it * NBUCK + t * 4 + j] = base;
        base += h0[j];
    }
}

__global__ void k_scatter_all() {
    int i = blockIdx.x * blockDim.x + threadIdx.x;
    int it = blockIdx.y;
    if (i >= N_ROWS) return;
    unsigned long long p = d_packA[it * N_ROWS + i];
    unsigned int b = (unsigned int)(p >> 50);
    unsigned int pos = atomicAdd(&d_woffsA[it * NBUCK + b], 1u);
    d_pack2A[it * N_ROWS + pos] = p;
}

// One thread per (iteration, bucket); re-zeroes hist for next use.
__global__ void k_bsort_all() {
    int g = blockIdx.x * blockDim.x + threadIdx.x;
    if (g >= MAXK * NBUCK) return;
    int it = g / NBUCK;
    unsigned int start = d_offsA[g];
    unsigned int cnt = d_histA[g];
    if (cnt > 64u) cnt = 64u;   // Poisson(7.3): P(>64) ~ 1e-30
    unsigned long long a[64];
    const unsigned long long* src = d_pack2A + it * N_ROWS;
    for (unsigned int i = 0; i < cnt; i++) a[i] = src[start + i];
    for (unsigned int i = 1; i < cnt; i++) {
        unsigned long long key = a[i];
        int j = (int)i - 1;
        while (j >= 0 && a[j] > key) { a[j + 1] = a[j]; j--; }
        a[j + 1] = key;
    }
    int* dst = d_permA + it * N_ROWS;
    for (unsigned int i = 0; i < cnt; i++)
        dst[start + i] = (int)(a[i] & 0x7FFFull);
    d_histA[g] = 0u;
}

// ============================================================================
// Candidate evaluation (64 rows x 100 candidates, 400 threads, 4x4 tile)
// + fused final v-reduce/argmax in the last block (atomic-counter pattern).
// ============================================================================
#define BM 64
#define KT 56
#define NTILE (D_IN / KT)   // 14

__global__ void __launch_bounds__(400, 3)
k_cand(const float* __restrict__ X, const float* __restrict__ Y,
       int batch, int n, int kit) {
    __shared__ float As[KT][68];
    __shared__ float Bs[KT][NC];
    __shared__ float ekS[BM][N_CLS];
    __shared__ float betaS[MAXK * N_CLS];
    __shared__ int idxS[BM];
    __shared__ int sflag;
    __shared__ float vS[NC];

    int tid = threadIdx.x;
    int tx = tid >> 4;                 // 0..24 candidate group (4 cands)
    int ty = tid & 15;                 // 0..15 row group (4 rows)
    int row0 = blockIdx.x * BM;
    const float* Wit = d_Wr + kit * WSZ;
    const int* perm = d_permA + kit * N_ROWS;

    if (tid < BM) {
        int g = row0 + tid;
        idxS[tid] = (g < batch) ? perm[g] : -1;
    }
    if (tid >= 64 && tid < 64 + n * N_CLS) betaS[tid - 64] = d_beta[tid - 64];
    __syncthreads();
    // ek = Y[idx] - H[idx,:n] @ beta (ascending-q order)
    for (int t = tid; t < BM * N_CLS; t += 400) {
        int r = t / N_CLS, j = t % N_CLS;
        int idx = idxS[r];
        float e = 0.0f;
        if (idx >= 0) {
            float yv = 0.0f;
            const float* hr = d_H + (size_t)idx * MAXK;
            for (int q = 0; q < n; q++) yv += hr[q] * betaS[q * N_CLS + j];
            e = Y[idx * N_CLS + j] - yv;
        }
        ekS[r][j] = e;
    }

    float acc[16];
#pragma unroll
    for (int i = 0; i < 16; i++) acc[i] = 0.0f;

    for (int t14 = 0; t14 < NTILE; t14++) {
        int k0 = t14 * KT;
        __syncthreads();
        for (int e = tid; e < BM * (KT / 4); e += 400) {
            int r = e / (KT / 4);
            int v = e % (KT / 4);
            int idx = idxS[r];
            float4 x = make_float4(0.f, 0.f, 0.f, 0.f);
            if (idx >= 0)
                x = *reinterpret_cast<const float4*>(X + (size_t)idx * D_IN + k0 + v * 4);
            As[v * 4 + 0][r] = x.x;
            As[v * 4 + 1][r] = x.y;
            As[v * 4 + 2][r] = x.z;
            As[v * 4 + 3][r] = x.w;
        }
        {
            const float4* src = reinterpret_cast<const float4*>(Wit + k0 * NC);
            float4* dst = reinterpret_cast<float4*>(&Bs[0][0]);
            for (int e = tid; e < KT * NC / 4; e += 400) dst[e] = src[e];
        }
        __syncthreads();
#pragma unroll 8
        for (int q = 0; q < KT; q++) {
            float4 a = *reinterpret_cast<const float4*>(&As[q][ty * 4]);
            float4 b = *reinterpret_cast<const float4*>(&Bs[q][tx * 4]);
            acc[0]  += a.x * b.x;  acc[1]  += a.x * b.y;
            acc[2]  += a.x * b.z;  acc[3]  += a.x * b.w;
            acc[4]  += a.y * b.x;  acc[5]  += a.y * b.y;
            acc[6]  += a.y * b.z;  acc[7]  += a.y * b.w;
            acc[8]  += a.z * b.x;  acc[9]  += a.z * b.y;
            acc[10] += a.z * b.z;  acc[11] += a.z * b.w;
            acc[12] += a.w * b.x;  acc[13] += a.w * b.y;
            acc[14] += a.w * b.z;  acc[15] += a.w * b.w;
        }
    }

    // Epilogue: h = sigmoid(acc + bias), masked.
    const float* bit = d_br + kit * NC;
    float bj[4];
#pragma unroll
    for (int j = 0; j < 4; j++) bj[j] = bit[tx * 4 + j];
    bool vld[4];
#pragma unroll
    for (int i = 0; i < 4; i++) vld[i] = (idxS[ty * 4 + i] >= 0);

    float h[16];
#pragma unroll
    for (int i = 0; i < 4; i++)
#pragma unroll
        for (int j = 0; j < 4; j++) {
            float z = acc[i * 4 + j] + bj[j];
            h[i * 4 + j] = vld[i] ? (1.0f / (1.0f + expf(-z))) : 0.0f;
        }

    // 16-lane group reductions (two groups per warp; tail warp has one).
    int lane = tid & 31;
    unsigned int msk = 0xFFFFu << (lane & 16);
    int pbase = blockIdx.x * 1104 + (tx * 4) * 11;

#pragma unroll
    for (int j = 0; j < 4; j++) {
        float s2 = h[j] * h[j] + h[4 + j] * h[4 + j] +
                   h[8 + j] * h[8 + j] + h[12 + j] * h[12 + j];
#pragma unroll
        for (int o = 1; o < 16; o <<= 1) s2 += __shfl_xor_sync(msk, s2, o);
        if (ty == 0) d_part[pbase + j * 11 + 10] = s2;
    }
#pragma unroll
    for (int jc = 0; jc < N_CLS; jc++) {
        float e0 = ekS[ty * 4 + 0][jc];
        float e1 = ekS[ty * 4 + 1][jc];
        float e2 = ekS[ty * 4 + 2][jc];
        float e3 = ekS[ty * 4 + 3][jc];
#pragma unroll
        for (int j = 0; j < 4; j++) {
            float m = e0 * h[j] + e1 * h[4 + j] + e2 * h[8 + j] + e3 * h[12 + j];
#pragma unroll
            for (int o = 1; o < 16; o <<= 1) m += __shfl_xor_sync(msk, m, o);
            if (ty == 0) d_part[pbase + j * 11 + jc] = m;
        }
    }

    // ---- Fused final reduce + argmax in the last block to finish ----
    __syncthreads();
    if (tid == 0) {
        __threadfence();
        int o = atomicAdd(&d_ctr1, 1);
        sflag = (o == (int)gridDim.x - 1) ? 1 : 0;
    }
    __syncthreads();
    if (sflag) {
        __threadfence();                 // acquire all blocks' partials
        int nb = (int)gridDim.x;
        int c = tid >> 2, p = tid & 3;   // 100 cands x 4 strides
        double m[N_CLS];
        double s2 = 0.0;
        for (int j = 0; j < N_CLS; j++) m[j] = 0.0;
        for (int b = p; b < nb; b += 4) {
            const float* pp = &d_part[b * 1104 + c * 11];
            for (int j = 0; j < N_CLS; j++) m[j] += (double)pp[j];
            s2 += (double)pp[10];
        }
        unsigned int m4 = 0xFu << (lane & ~3);
        for (int j = 0; j < N_CLS; j++) {
            m[j] += __shfl_xor_sync(m4, m[j], 1);
            m[j] += __shfl_xor_sync(m4, m[j], 2);
        }
        s2 += __shfl_xor_sync(m4, s2, 1);
        s2 += __shfl_xor_sync(m4, s2, 2);
        if (p == 0) {
            double num = 0.0;
            for (int j = 0; j < N_CLS; j++) num += m[j] * m[j];
            vS[c] = (float)(num / (10.0 * s2));
        }
        __syncthreads();
        if (tid == 0) {
            float best = -1.0f;
            int bi = 0;
            for (int i = 0; i < NC; i++)
                if (vS[i] > best) { best = vS[i]; bi = i; }
            d_best = bi;
            d_ctr1 = 0;                  // reset for next launch/replay
        }
    }
}

// ============================================================================
// h_c = sigmoid(X @ W_best + b_best); W loaded coalesced from d_WrT.
// ============================================================================
__global__ void k_hc(const float* __restrict__ X, float* __restrict__ out, int kit) {
    __shared__ float Wc[D_IN];
    __shared__ float s_b;
    int best = d_best;
    const float* wt = d_WrT + (size_t)(kit * NC + best) * D_IN;
    for (int t = threadIdx.x; t < D_IN; t += 256) Wc[t] = wt[t];
    if (threadIdx.x == 0) s_b = d_br[kit * NC + best];
    __syncthreads();
    int w = threadIdx.x >> 5, lane = threadIdx.x & 31;
    int row = blockIdx.x * 8 + w;
    if (row < N_ROWS) {
        const float* xr = X + (size_t)row * D_IN;
        float s = 0.0f;
        for (int q = lane; q < D_IN; q += 32) s += xr[q] * Wc[q];
#pragma unroll
        for (int o = 16; o; o >>= 1) s += __shfl_down_sync(0xffffffffu, s, o);
        if (lane == 0) {
            float h = 1.0f / (1.0f + expf(-(s + s_b)));
            d_H[row * MAXK + kit] = h;
        }
    }
    if (blockIdx.x == 0) {
        for (int t = threadIdx.x; t < D_IN; t += 256) out[t * MAXK + kit] = Wc[t];
        if (threadIdx.x == 0) out[D_IN * MAXK + kit] = s_b;
    }
}

// ============================================================================
// Incremental Gram (new row/col of H^T H + row of H^T Y) with fused
// reduce -> Cholesky -> solve in the last block.
// ============================================================================
__global__ void k_gram(const float* __restrict__ Y, float* __restrict__ out, int kit) {
    __shared__ int sflag;
    __shared__ double Ls[12][12], Cs[12][10];
    int tid = threadIdx.x;                 // 256
    int entry = tid >> 3, s = tid & 7;
    int n = kit + 1;
    int nent = n + N_CLS;
    double acc = 0.0;
    int r0 = blockIdx.x * 240;
    if (entry < nent) {
        if (entry < n) {
            for (int i = 0; i < 30; i++) {
                int r = r0 + s + 8 * i;
                double hk = (double)d_H[r * MAXK + kit];
                acc += hk * (double)d_H[r * MAXK + entry];
            }
        } else {
            int cls = entry - n;
            for (int i = 0; i < 30; i++) {
                int r = r0 + s + 8 * i;
                double hk = (double)d_H[r * MAXK + kit];
                acc += hk * (double)Y[r * N_CLS + cls];
            }
        }
    }
    unsigned int lane = tid & 31;
    unsigned int m8 = 0xFFu << (lane & ~7);
    acc += __shfl_xor_sync(m8, acc, 1);
    acc += __shfl_xor_sync(m8, acc, 2);
    acc += __shfl_xor_sync(m8, acc, 4);
    if (s == 0) d_gpart[blockIdx.x * 32 + entry] = acc;

    __syncthreads();
    if (tid == 0) {
        __threadfence();
        int o = atomicAdd(&d_ctr2, 1);
        sflag = (o == (int)gridDim.x - 1) ? 1 : 0;
    }
    __syncthreads();
    if (!sflag) return;
    __threadfence();

    // ---- last block: reduce partials, update G/C, Cholesky, solve ----
    int t = tid;
    if (t < 32 && t < nent) {
        double a0 = 0, a1 = 0, a2 = 0, a3 = 0, a4 = 0;
        for (int b = 0; b + 5 <= 125; b += 5) {
            a0 += d_gpart[(b + 0) * 32 + t];
            a1 += d_gpart[(b + 1) * 32 + t];
            a2 += d_gpart[(b + 2) * 32 + t];
            a3 += d_gpart[(b + 3) * 32 + t];
            a4 += d_gpart[(b + 4) * 32 + t];
        }
        double sum = ((a0 + a1) + (a2 + a3)) + a4;
        if (t < n) {
            d_G[(n - 1) * 12 + t] = sum;
            d_G[t * 12 + (n - 1)] = sum;
        } else {
            d_C[(n - 1) * 10 + (t - n)] = sum;
        }
    }
    __syncthreads();
    for (int e = t; e < n * n; e += 256) Ls[e / n][e % n] = d_G[(e / n) * 12 + (e % n)];
    for (int e = t; e < n * 10; e += 256) Cs[e / 10][e % 10] = d_C[e];
    __syncthreads();
    if (t < 32) {
        for (int j = 0; j < n; j++) {
            if (t == 0) {
                double v = Ls[j][j];
                for (int p = 0; p < j; p++) v -= Ls[j][p] * Ls[j][p];
                Ls[j][j] = sqrt(v);
            }
            __syncwarp();
            if (t > j && t < n) {
                double v = Ls[t][j];
                for (int p = 0; p < j; p++) v -= Ls[t][p] * Ls[j][p];
                Ls[t][j] = v / Ls[j][j];
            }
            __syncwarp();
        }
    }
    __syncthreads();
    if (t < N_CLS) {
        double z[12];
        for (int i = 0; i < n; i++) {
            double v = Cs[i][t];
            for (int p = 0; p < i; p++) v -= Ls[i][p] * z[p];
            z[i] = v / Ls[i][i];
        }
        for (int i = n - 1; i >= 0; i--) {
            double v = z[i];
            for (int p = i + 1; p < n; p++) v -= Ls[p][i] * z[p];
            z[i] = v / Ls[i][i];
        }
        for (int i = 0; i < n; i++) {
            d_beta[i * 10 + t] = (float)z[i];
            if (n == MAXK) out[D_IN * MAXK + MAXK + i * 10 + t] = (float)z[i];
        }
    }
    if (t == 0) d_ctr2 = 0;
}

// ============================================================================
// Launch — 46 graph nodes total
// ============================================================================
extern "C" void kernel_launch(void* const* d_in, const int* in_sizes, int n_in,
                              void* d_out, int out_size) {
    const float* X = (const float*)d_in[0];
    const float* Y = (const float*)d_in[1];
    float* out = (float*)d_out;

    k_init<<<1, 32>>>();
    k_genc_all<<<(MAXK * (WSZ + NC) + 255) / 256, 256>>>();

    // All 12 permutations up front (2 stable shuffle rounds, batched).
    dim3 sg((N_ROWS + 255) / 256, MAXK);
    for (int r = 0; r < 2; r++) {
        k_genhist_all<<<sg, 256>>>(r);
        k_scan_all<<<MAXK, 1024>>>();
        k_scatter_all<<<sg, 256>>>();
        k_bsort_all<<<(MAXK * NBUCK + 127) / 128, 128>>>();
    }

    int batch = INITB;
    for (int k = 0; k < MAXK; k++) {
        int nb = (batch + BM - 1) / BM;
        k_cand<<<nb, 400>>>(X, Y, batch, k, k);
        k_hc<<<(N_ROWS + 7) / 8, 256>>>(X, out, k);
        k_gram<<<125, 256>>>(Y, out, k);
        batch += BINC;
    }
}